// round 15
// baseline (speedup 1.0000x reference)
#include <cuda_runtime.h>
#include <cstdint>

// Problem constants (fixed shapes)
#define BS    16
#define DIM   4096
#define NH    32
#define DH    128
#define SEQ   4096
#define NCOL  4096   // NH*DH
#define KS    64     // K-split for the 16xN GEMMs

#define WEIGHT_ELEMS (BS * NH * SEQ)   // 2097152
#define BN (BS * NCOL)                 // 65536

// Scratch (device globals; no allocation allowed)
__device__ float g_qkv[3 * BN];             // q,k,v : [mat][b][h*128+d]
__device__ float g_part[3 * KS * BN];       // qkv GEMM k-split partials (L2-resident)
__device__ float g_ctx[BN];                 // attention context [b][h*128+d]
__device__ float g_cpart[KS * BN];          // out-proj k-split partials (L2-resident)

__device__ __forceinline__ void cp16(uint32_t dst_sh, const void* src) {
    asm volatile("cp.async.cg.shared.global [%0], [%1], 16;"
                 :: "r"(dst_sh), "l"(src));
}

// ---------------------------------------------------------------------------
// 16xK @ KxN GEMM body, cp.async double-buffered W tiles:
//   128 threads, each owns 2 consecutive output columns x all 16 batch rows
//   (fma.rn.f32x2). Block covers 256 columns x 64 K-rows.
//   W streamed via cp.async.cg (16B/thread) into 2 x 8KB smem buffers
//   (8 rows x 1KB per group); compute always reads smem (LDS.64 W broadcast-
//   free + LDS.128 X), so DRAM latency is hidden by the prefetch pipeline.
//   smem = 4KB X + 16KB W = 20KB -> occupancy 8 retained (regs ~48).
// ---------------------------------------------------------------------------
__device__ __forceinline__ void gemm16_body(const float* __restrict__ X,
                                            const float* __restrict__ W,
                                            float* __restrict__ part)
{
    __shared__ __align__(16) float xs[64][16];       // 4KB
    __shared__ __align__(16) float wt[2][8][256];    // 16KB (2 x 8 rows x 1KB)

    const int tid = threadIdx.x;
    const int j2  = blockIdx.x * 128 + tid;          // global float2 col index
    const int d0  = blockIdx.y * (DIM / KS);         // 64 rows per split

    // stage all 64 K-rows x 16 batch of X
#pragma unroll
    for (int i = tid; i < 1024; i += 128) {
        int b = i >> 6, dd = i & 63;
        xs[dd][b] = X[b * DIM + d0 + dd];
    }

    unsigned long long acc[16];
#pragma unroll
    for (int i = 0; i < 16; i++) acc[i] = 0ull;

    const uint32_t xs_sh = (uint32_t)__cvta_generic_to_shared(&xs[0][0]);
    const uint32_t wt_sh = (uint32_t)__cvta_generic_to_shared(&wt[0][0][0]);
    // base of this block's W panel (256 cols starting at blockIdx.x*256)
    const char* Wp = (const char*)(W + (size_t)d0 * NCOL + blockIdx.x * 256);

    // issue one 8-row group (8KB): 4 x 16B per thread
    auto issue = [&](int g, int buf) {
        const char* src = Wp + (size_t)g * 8 * (NCOL * 4);
#pragma unroll
        for (int i = 0; i < 4; i++) {
            int idx = i * 2048 + tid * 16;           // byte idx within 8KB group
            int r   = idx >> 10;                      // row in group
            int cb  = idx & 1023;                     // col byte
            cp16(wt_sh + buf * 8192 + idx, src + (size_t)r * (NCOL * 4) + cb);
        }
        asm volatile("cp.async.commit_group;");
    };

    issue(0, 0);   // prologue

#pragma unroll
    for (int g = 0; g < 8; g++) {
        if (g < 7) {
            issue(g + 1, (g + 1) & 1);
            asm volatile("cp.async.wait_group 1;");
        } else {
            asm volatile("cp.async.wait_group 0;");
        }
        __syncthreads();

        const float* wrow = &wt[g & 1][0][0];
#pragma unroll
        for (int r = 0; r < 8; r++) {
            float2 w = *(const float2*)(wrow + r * 256 + tid * 2);
            unsigned long long wx, wy;
            asm("mov.b64 %0, {%1, %1};" : "=l"(wx) : "f"(w.x));
            asm("mov.b64 %0, {%1, %1};" : "=l"(wy) : "f"(w.y));
            const uint32_t ra = xs_sh + (g * 8 + r) * 64;
#pragma unroll
            for (int bh = 0; bh < 4; bh++) {
                unsigned long long xa, xb;   // batches {4bh,4bh+1}, {4bh+2,4bh+3}
                asm("ld.shared.v2.b64 {%0, %1}, [%2];"
                    : "=l"(xa), "=l"(xb) : "r"(ra + bh * 16));
                asm("fma.rn.f32x2 %0, %1, %2, %0;" : "+l"(acc[bh * 4 + 0]) : "l"(xa), "l"(wx));
                asm("fma.rn.f32x2 %0, %1, %2, %0;" : "+l"(acc[bh * 4 + 1]) : "l"(xa), "l"(wy));
                asm("fma.rn.f32x2 %0, %1, %2, %0;" : "+l"(acc[bh * 4 + 2]) : "l"(xb), "l"(wx));
                asm("fma.rn.f32x2 %0, %1, %2, %0;" : "+l"(acc[bh * 4 + 3]) : "l"(xb), "l"(wy));
            }
        }
        __syncthreads();   // compute done before next issue overwrites this buffer
    }

    float2* P2 = (float2*)part;
#pragma unroll
    for (int bp = 0; bp < 8; bp++) {
        float c0l, c0h, c1l, c1h;
        asm("mov.b64 {%0, %1}, %2;" : "=f"(c0l), "=f"(c0h) : "l"(acc[bp * 2]));
        asm("mov.b64 {%0, %1}, %2;" : "=f"(c1l), "=f"(c1h) : "l"(acc[bp * 2 + 1]));
        P2[(bp * 2 + 0) * (NCOL / 2) + j2] = make_float2(c0l, c1l);
        P2[(bp * 2 + 1) * (NCOL / 2) + j2] = make_float2(c0h, c1h);
    }
}

__global__ __launch_bounds__(128, 8)
void gemm_qkv(const float* __restrict__ x, const float* __restrict__ wq,
              const float* __restrict__ wk, const float* __restrict__ wv)
{
    const float* W = (blockIdx.z == 0) ? wq : (blockIdx.z == 1 ? wk : wv);
    float* part = g_part + ((size_t)blockIdx.z * KS + blockIdx.y) * BN;
    gemm16_body(x, W, part);
}

__global__ __launch_bounds__(128, 8)
void gemm_out(const float* __restrict__ wo)
{
    float* part = g_cpart + (size_t)blockIdx.y * BN;
    gemm16_body(g_ctx, wo, part);
}

__global__ __launch_bounds__(256)
void reduce_qkv()
{
    int i = blockIdx.x * 256 + threadIdx.x;
    if (i < 3 * BN) {
        int mat = i >> 16;
        int r   = i & (BN - 1);
        const float* p = g_part + (size_t)mat * KS * BN + r;
        float s = 0.f;
#pragma unroll 8
        for (int k = 0; k < KS; k++) s += p[(size_t)k * BN];
        g_qkv[i] = s;
    }
}

__global__ __launch_bounds__(256)
void reduce_out(float* __restrict__ out)
{
    int i = blockIdx.x * 256 + threadIdx.x;
    if (i < BN) {
        const float* p = g_cpart + i;
        float s = 0.f;
#pragma unroll 8
        for (int k = 0; k < KS; k++) s += p[(size_t)k * BN];
        __stcs(&out[i], s);
    }
}

// ---------------------------------------------------------------------------
// Fused attention per (b,h), 512 threads — two-pass form (rounds 4/7/9/12/14;
// ~6.8 TB/s effective; single wave of 512 resident blocks). DO NOT SPLIT
// (regressed +30us in rounds 3, 6, 8). K/V streamed with __ldcs; weight
// output written with __stcs (write-once, never re-read).
// ---------------------------------------------------------------------------
__global__ __launch_bounds__(512)
void attn_kernel(const float* __restrict__ ck, const float* __restrict__ cv,
                 const float* __restrict__ mask, float* __restrict__ out)
{
    const int b = blockIdx.x, h = blockIdx.y;
    const int tid = threadIdx.x, lane = tid & 31, wp = tid >> 5;

    __shared__ float sc[SEQ];          // scores -> exp weights
    __shared__ __align__(16) float qs[DH];
    __shared__ float redm[16], reds[16];
    __shared__ __align__(16) float cp[16][DH];

    if (tid < DH) qs[tid] = g_qkv[(size_t)b * NCOL + h * DH + tid];
    __syncthreads();

    const float4 qf = ((const float4*)qs)[lane];
    const float4* kb4 = (const float4*)(ck + ((size_t)b << 24) + (size_t)h * DH);
    const float4* kn4 = (const float4*)(g_qkv + BN + (size_t)b * NCOL + h * DH);
    const float scale = 0.08838834764831845f;                        // 1/sqrt(128)
    float* wout = out + ((size_t)(b * NH + h)) * SEQ;

    // pass 1: scores (16 warps, 256 rows each); streaming K loads
#pragma unroll 4
    for (int k = wp; k < SEQ; k += 16) {
        float4 kf = (k == SEQ - 1) ? kn4[lane]
                                   : __ldcs(&kb4[(size_t)k * (NCOL / 4) + lane]);
        float p = kf.x * qf.x + kf.y * qf.y + kf.z * qf.z + kf.w * qf.w;
        p += __shfl_xor_sync(0xffffffffu, p, 16);
        p += __shfl_xor_sync(0xffffffffu, p, 8);
        p += __shfl_xor_sync(0xffffffffu, p, 4);
        p += __shfl_xor_sync(0xffffffffu, p, 2);
        p += __shfl_xor_sync(0xffffffffu, p, 1);
        if (lane == 0) sc[k] = p * scale + __ldg(&mask[k]);
    }
    __syncthreads();

    // coalesced weight output write (streaming) + max reduce
    float m = -1e30f;
    for (int i = tid; i < SEQ; i += 512) {
        float s = sc[i];
        __stcs(&wout[i], s);
        m = fmaxf(m, s);
    }
#pragma unroll
    for (int o = 16; o; o >>= 1) m = fmaxf(m, __shfl_xor_sync(0xffffffffu, m, o));
    if (lane == 0) redm[wp] = m;
    __syncthreads();
    float M = redm[0];
#pragma unroll
    for (int i = 1; i < 16; i++) M = fmaxf(M, redm[i]);

    float sum = 0.f;
    for (int i = tid; i < SEQ; i += 512) {
        float e = __expf(sc[i] - M);
        sc[i] = e;
        sum += e;
    }
#pragma unroll
    for (int o = 16; o; o >>= 1) sum += __shfl_xor_sync(0xffffffffu, sum, o);
    if (lane == 0) reds[wp] = sum;
    __syncthreads();
    float S = 0.f;
#pragma unroll
    for (int i = 0; i < 16; i++) S += reds[i];
    const float rinv = 1.f / S;

    // pass 2: ctx[d] = sum_k attn[k] * V[b,k,h,d]; 16 k-stripes, streaming
    const float4* vrow4 = (const float4*)(cv + ((size_t)b << 24) + (size_t)h * DH);
    float4 a4 = make_float4(0.f, 0.f, 0.f, 0.f);
    const int k0 = wp * 256;
    const int k1 = k0 + 256 - (wp == 15 ? 1 : 0);   // stripe 15 stops at 4094
#pragma unroll 8
    for (int k = k0; k < k1; k++) {
        float w = sc[k];
        float4 v = __ldcs(&vrow4[(size_t)k * (NCOL / 4) + lane]);
        a4.x += w * v.x; a4.y += w * v.y; a4.z += w * v.z; a4.w += w * v.w;
    }
    if (wp == 15) {
        float w = sc[SEQ - 1];
        float4 v = ((const float4*)(g_qkv + 2 * BN + (size_t)b * NCOL + h * DH))[lane];
        a4.x += w * v.x; a4.y += w * v.y; a4.z += w * v.z; a4.w += w * v.w;
    }
    ((float4*)cp[wp])[lane] = a4;
    __syncthreads();

    if (tid < DH) {
        float s = 0.f;
#pragma unroll
        for (int i = 0; i < 16; i++) s += cp[i][tid];
        g_ctx[(size_t)b * NCOL + h * DH + tid] = s * rinv;
    }
}

// ---------------------------------------------------------------------------
extern "C" void kernel_launch(void* const* d_in, const int* in_sizes, int n_in,
                              void* d_out, int out_size)
{
    const float* x    = (const float*)d_in[0];
    const float* mask = (const float*)d_in[1];
    const float* wq   = (const float*)d_in[2];
    const float* wk   = (const float*)d_in[3];
    const float* wv   = (const float*)d_in[4];
    const float* wo   = (const float*)d_in[5];
    const float* ck   = (const float*)d_in[6];
    const float* cv   = (const float*)d_in[7];
    float* out = (float*)d_out;

    gemm_qkv<<<dim3(16, KS, 3), 128>>>(x, wq, wk, wv);
    reduce_qkv<<<(3 * BN) / 256, 256>>>();
    attn_kernel<<<dim3(BS, NH), 512>>>(ck, cv, mask, out);
    gemm_out<<<dim3(16, KS, 1), 128>>>(wo);
    reduce_out<<<BN / 256, 256>>>(out + WEIGHT_ELEMS);
}

// round 16
// speedup vs baseline: 1.0111x; 1.0111x over previous
#include <cuda_runtime.h>
#include <cstdint>

// Problem constants (fixed shapes)
#define BS    16
#define DIM   4096
#define NH    32
#define DH    128
#define SEQ   4096
#define NCOL  4096   // NH*DH
#define KS    64     // K-split for the 16xN GEMMs

#define WEIGHT_ELEMS (BS * NH * SEQ)   // 2097152
#define BN (BS * NCOL)                 // 65536

// Scratch (device globals; no allocation allowed)
__device__ float g_qkv[3 * BN];             // q,k,v : [mat][b][h*128+d]
__device__ float g_part[3 * KS * BN];       // qkv GEMM k-split partials (L2-resident)
__device__ float g_ctx[BN];                 // attention context [b][h*128+d]
__device__ float g_cpart[KS * BN];          // out-proj k-split partials (L2-resident)

__device__ __forceinline__ void cp16(uint32_t dst_sh, const void* src) {
    asm volatile("cp.async.cg.shared.global [%0], [%1], 16;"
                 :: "r"(dst_sh), "l"(src));
}

// ---------------------------------------------------------------------------
// 16xK @ KxN GEMM body, cp.async double-buffered W tiles:
//   128 threads, each owns 2 consecutive output columns x all 16 batch rows
//   (fma.rn.f32x2). Block covers 256 columns x 64 K-rows.
//   W streamed via cp.async.cg (16B/thread) into 2 x 8KB smem buffers
//   (8 rows x 1KB per group); compute always reads smem (LDS.64 W broadcast-
//   free + LDS.128 X), so DRAM latency is hidden by the prefetch pipeline.
//   smem = 4KB X + 16KB W = 20KB -> occupancy 8 retained (regs ~48).
// ---------------------------------------------------------------------------
__device__ __forceinline__ void gemm16_body(const float* __restrict__ X,
                                            const float* __restrict__ W,
                                            float* __restrict__ part)
{
    __shared__ __align__(16) float xs[64][16];       // 4KB
    __shared__ __align__(16) float wt[2][8][256];    // 16KB (2 x 8 rows x 1KB)

    const int tid = threadIdx.x;
    const int j2  = blockIdx.x * 128 + tid;          // global float2 col index
    const int d0  = blockIdx.y * (DIM / KS);         // 64 rows per split

    // stage all 64 K-rows x 16 batch of X
#pragma unroll
    for (int i = tid; i < 1024; i += 128) {
        int b = i >> 6, dd = i & 63;
        xs[dd][b] = X[b * DIM + d0 + dd];
    }

    unsigned long long acc[16];
#pragma unroll
    for (int i = 0; i < 16; i++) acc[i] = 0ull;

    const uint32_t xs_sh = (uint32_t)__cvta_generic_to_shared(&xs[0][0]);
    const uint32_t wt_sh = (uint32_t)__cvta_generic_to_shared(&wt[0][0][0]);
    // base of this block's W panel (256 cols starting at blockIdx.x*256)
    const char* Wp = (const char*)(W + (size_t)d0 * NCOL + blockIdx.x * 256);

    // issue one 8-row group (8KB): 4 x 16B per thread
    auto issue = [&](int g, int buf) {
        const char* src = Wp + (size_t)g * 8 * (NCOL * 4);
#pragma unroll
        for (int i = 0; i < 4; i++) {
            int idx = i * 2048 + tid * 16;           // byte idx within 8KB group
            int r   = idx >> 10;                      // row in group
            int cb  = idx & 1023;                     // col byte
            cp16(wt_sh + buf * 8192 + idx, src + (size_t)r * (NCOL * 4) + cb);
        }
        asm volatile("cp.async.commit_group;");
    };

    issue(0, 0);   // prologue

#pragma unroll
    for (int g = 0; g < 8; g++) {
        if (g < 7) {
            issue(g + 1, (g + 1) & 1);
            asm volatile("cp.async.wait_group 1;");
        } else {
            asm volatile("cp.async.wait_group 0;");
        }
        __syncthreads();

        const float* wrow = &wt[g & 1][0][0];
#pragma unroll
        for (int r = 0; r < 8; r++) {
            float2 w = *(const float2*)(wrow + r * 256 + tid * 2);
            unsigned long long wx, wy;
            asm("mov.b64 %0, {%1, %1};" : "=l"(wx) : "f"(w.x));
            asm("mov.b64 %0, {%1, %1};" : "=l"(wy) : "f"(w.y));
            const uint32_t ra = xs_sh + (g * 8 + r) * 64;
#pragma unroll
            for (int bh = 0; bh < 4; bh++) {
                unsigned long long xa, xb;   // batches {4bh,4bh+1}, {4bh+2,4bh+3}
                asm("ld.shared.v2.b64 {%0, %1}, [%2];"
                    : "=l"(xa), "=l"(xb) : "r"(ra + bh * 16));
                asm("fma.rn.f32x2 %0, %1, %2, %0;" : "+l"(acc[bh * 4 + 0]) : "l"(xa), "l"(wx));
                asm("fma.rn.f32x2 %0, %1, %2, %0;" : "+l"(acc[bh * 4 + 1]) : "l"(xa), "l"(wy));
                asm("fma.rn.f32x2 %0, %1, %2, %0;" : "+l"(acc[bh * 4 + 2]) : "l"(xb), "l"(wx));
                asm("fma.rn.f32x2 %0, %1, %2, %0;" : "+l"(acc[bh * 4 + 3]) : "l"(xb), "l"(wy));
            }
        }
        __syncthreads();   // compute done before next issue overwrites this buffer
    }

    float2* P2 = (float2*)part;
#pragma unroll
    for (int bp = 0; bp < 8; bp++) {
        float c0l, c0h, c1l, c1h;
        asm("mov.b64 {%0, %1}, %2;" : "=f"(c0l), "=f"(c0h) : "l"(acc[bp * 2]));
        asm("mov.b64 {%0, %1}, %2;" : "=f"(c1l), "=f"(c1h) : "l"(acc[bp * 2 + 1]));
        P2[(bp * 2 + 0) * (NCOL / 2) + j2] = make_float2(c0l, c1l);
        P2[(bp * 2 + 1) * (NCOL / 2) + j2] = make_float2(c0h, c1h);
    }
}

__global__ __launch_bounds__(128, 8)
void gemm_qkv(const float* __restrict__ x, const float* __restrict__ wq,
              const float* __restrict__ wk, const float* __restrict__ wv)
{
    const float* W = (blockIdx.z == 0) ? wq : (blockIdx.z == 1 ? wk : wv);
    float* part = g_part + ((size_t)blockIdx.z * KS + blockIdx.y) * BN;
    gemm16_body(x, W, part);
}

__global__ __launch_bounds__(128, 8)
void gemm_out(const float* __restrict__ wo)
{
    float* part = g_cpart + (size_t)blockIdx.y * BN;
    gemm16_body(g_ctx, wo, part);
}

__global__ __launch_bounds__(256)
void reduce_qkv()
{
    int i = blockIdx.x * 256 + threadIdx.x;
    if (i < 3 * BN) {
        int mat = i >> 16;
        int r   = i & (BN - 1);
        const float* p = g_part + (size_t)mat * KS * BN + r;
        float s = 0.f;
#pragma unroll 8
        for (int k = 0; k < KS; k++) s += p[(size_t)k * BN];
        g_qkv[i] = s;
    }
}

__global__ __launch_bounds__(256)
void reduce_out(float* __restrict__ out)
{
    int i = blockIdx.x * 256 + threadIdx.x;
    if (i < BN) {
        const float* p = g_cpart + i;
        float s = 0.f;
#pragma unroll 8
        for (int k = 0; k < KS; k++) s += p[(size_t)k * BN];
        __stcs(&out[i], s);
    }
}

// ---------------------------------------------------------------------------
// Fused attention per (b,h), 512 threads — two-pass form (rounds 4/7/9/12/14;
// ~6.8 TB/s effective; single wave of 512 resident blocks). DO NOT SPLIT
// (regressed +30us in rounds 3, 6, 8). K/V streamed with __ldcs; weight
// output written with __stcs (write-once, never re-read).
// ---------------------------------------------------------------------------
__global__ __launch_bounds__(512)
void attn_kernel(const float* __restrict__ ck, const float* __restrict__ cv,
                 const float* __restrict__ mask, float* __restrict__ out)
{
    const int b = blockIdx.x, h = blockIdx.y;
    const int tid = threadIdx.x, lane = tid & 31, wp = tid >> 5;

    __shared__ float sc[SEQ];          // scores -> exp weights
    __shared__ __align__(16) float qs[DH];
    __shared__ float redm[16], reds[16];
    __shared__ __align__(16) float cp[16][DH];

    if (tid < DH) qs[tid] = g_qkv[(size_t)b * NCOL + h * DH + tid];
    __syncthreads();

    const float4 qf = ((const float4*)qs)[lane];
    const float4* kb4 = (const float4*)(ck + ((size_t)b << 24) + (size_t)h * DH);
    const float4* kn4 = (const float4*)(g_qkv + BN + (size_t)b * NCOL + h * DH);
    const float scale = 0.08838834764831845f;                        // 1/sqrt(128)
    float* wout = out + ((size_t)(b * NH + h)) * SEQ;

    // pass 1: scores (16 warps, 256 rows each); streaming K loads
#pragma unroll 4
    for (int k = wp; k < SEQ; k += 16) {
        float4 kf = (k == SEQ - 1) ? kn4[lane]
                                   : __ldcs(&kb4[(size_t)k * (NCOL / 4) + lane]);
        float p = kf.x * qf.x + kf.y * qf.y + kf.z * qf.z + kf.w * qf.w;
        p += __shfl_xor_sync(0xffffffffu, p, 16);
        p += __shfl_xor_sync(0xffffffffu, p, 8);
        p += __shfl_xor_sync(0xffffffffu, p, 4);
        p += __shfl_xor_sync(0xffffffffu, p, 2);
        p += __shfl_xor_sync(0xffffffffu, p, 1);
        if (lane == 0) sc[k] = p * scale + __ldg(&mask[k]);
    }
    __syncthreads();

    // coalesced weight output write (streaming) + max reduce
    float m = -1e30f;
    for (int i = tid; i < SEQ; i += 512) {
        float s = sc[i];
        __stcs(&wout[i], s);
        m = fmaxf(m, s);
    }
#pragma unroll
    for (int o = 16; o; o >>= 1) m = fmaxf(m, __shfl_xor_sync(0xffffffffu, m, o));
    if (lane == 0) redm[wp] = m;
    __syncthreads();
    float M = redm[0];
#pragma unroll
    for (int i = 1; i < 16; i++) M = fmaxf(M, redm[i]);

    float sum = 0.f;
    for (int i = tid; i < SEQ; i += 512) {
        float e = __expf(sc[i] - M);
        sc[i] = e;
        sum += e;
    }
#pragma unroll
    for (int o = 16; o; o >>= 1) sum += __shfl_xor_sync(0xffffffffu, sum, o);
    if (lane == 0) reds[wp] = sum;
    __syncthreads();
    float S = 0.f;
#pragma unroll
    for (int i = 0; i < 16; i++) S += reds[i];
    const float rinv = 1.f / S;

    // pass 2: ctx[d] = sum_k attn[k] * V[b,k,h,d]; 16 k-stripes, streaming
    const float4* vrow4 = (const float4*)(cv + ((size_t)b << 24) + (size_t)h * DH);
    float4 a4 = make_float4(0.f, 0.f, 0.f, 0.f);
    const int k0 = wp * 256;
    const int k1 = k0 + 256 - (wp == 15 ? 1 : 0);   // stripe 15 stops at 4094
#pragma unroll 8
    for (int k = k0; k < k1; k++) {
        float w = sc[k];
        float4 v = __ldcs(&vrow4[(size_t)k * (NCOL / 4) + lane]);
        a4.x += w * v.x; a4.y += w * v.y; a4.z += w * v.z; a4.w += w * v.w;
    }
    if (wp == 15) {
        float w = sc[SEQ - 1];
        float4 v = ((const float4*)(g_qkv + 2 * BN + (size_t)b * NCOL + h * DH))[lane];
        a4.x += w * v.x; a4.y += w * v.y; a4.z += w * v.z; a4.w += w * v.w;
    }
    ((float4*)cp[wp])[lane] = a4;
    __syncthreads();

    if (tid < DH) {
        float s = 0.f;
#pragma unroll
        for (int i = 0; i < 16; i++) s += cp[i][tid];
        g_ctx[(size_t)b * NCOL + h * DH + tid] = s * rinv;
    }
}

// ---------------------------------------------------------------------------
extern "C" void kernel_launch(void* const* d_in, const int* in_sizes, int n_in,
                              void* d_out, int out_size)
{
    const float* x    = (const float*)d_in[0];
    const float* mask = (const float*)d_in[1];
    const float* wq   = (const float*)d_in[2];
    const float* wk   = (const float*)d_in[3];
    const float* wv   = (const float*)d_in[4];
    const float* wo   = (const float*)d_in[5];
    const float* ck   = (const float*)d_in[6];
    const float* cv   = (const float*)d_in[7];
    float* out = (float*)d_out;

    gemm_qkv<<<dim3(16, KS, 3), 128>>>(x, wq, wk, wv);
    reduce_qkv<<<(3 * BN) / 256, 256>>>();
    attn_kernel<<<dim3(BS, NH), 512>>>(ck, cv, mask, out);
    gemm_out<<<dim3(16, KS, 1), 128>>>(wo);
    reduce_out<<<BN / 256, 256>>>(out + WEIGHT_ELEMS);
}

// round 17
// speedup vs baseline: 1.0123x; 1.0011x over previous
#include <cuda_runtime.h>
#include <cstdint>

// Problem constants (fixed shapes)
#define BS    16
#define DIM   4096
#define NH    32
#define DH    128
#define SEQ   4096
#define NCOL  4096   // NH*DH
#define KS    64     // K-split for the 16xN GEMMs

#define WEIGHT_ELEMS (BS * NH * SEQ)   // 2097152
#define BN (BS * NCOL)                 // 65536

// Scratch (device globals; no allocation allowed)
__device__ float g_qkv[3 * BN];             // q,k,v : [mat][b][h*128+d]
__device__ float g_part[3 * KS * BN];       // qkv GEMM k-split partials (L2-resident)
__device__ float g_ctx[BN];                 // attention context [b][h*128+d]
__device__ float g_cpart[KS * BN];          // out-proj k-split partials (L2-resident)

__device__ __forceinline__ void cp16(uint32_t dst_sh, const void* src) {
    asm volatile("cp.async.cg.shared.global [%0], [%1], 16;"
                 :: "r"(dst_sh), "l"(src));
}

// ---------------------------------------------------------------------------
// 16xK @ KxN GEMM body, 3-stage cp.async pipelined W tiles:
//   128 threads, each owns 2 consecutive output columns x all 16 batch rows
//   (fma.rn.f32x2). Block covers 256 columns x 64 K-rows.
//   W streamed via cp.async.cg into 3 x 8KB smem buffers; TWO 8KB groups in
//   flight per block at all times -> 128KB in flight per SM at occupancy 8
//   (2x the register-batch scheme; bytes-in-flight is the BW controller).
//   smem = 4KB X + 24KB W = 28KB; 8 x 28 = 224KB <= 228KB -> occupancy 8.
// ---------------------------------------------------------------------------
__device__ __forceinline__ void gemm16_body(const float* __restrict__ X,
                                            const float* __restrict__ W,
                                            float* __restrict__ part)
{
    __shared__ __align__(16) float xs[64][16];       // 4KB
    __shared__ __align__(16) float wt[3][8][256];    // 24KB (3 x 8 rows x 1KB)

    const int tid = threadIdx.x;
    const int j2  = blockIdx.x * 128 + tid;          // global float2 col index
    const int d0  = blockIdx.y * (DIM / KS);         // 64 rows per split

    // stage all 64 K-rows x 16 batch of X
#pragma unroll
    for (int i = tid; i < 1024; i += 128) {
        int b = i >> 6, dd = i & 63;
        xs[dd][b] = X[b * DIM + d0 + dd];
    }

    unsigned long long acc[16];
#pragma unroll
    for (int i = 0; i < 16; i++) acc[i] = 0ull;

    const uint32_t xs_sh = (uint32_t)__cvta_generic_to_shared(&xs[0][0]);
    const uint32_t wt_sh = (uint32_t)__cvta_generic_to_shared(&wt[0][0][0]);
    // base of this block's W panel (256 cols starting at blockIdx.x*256)
    const char* Wp = (const char*)(W + (size_t)d0 * NCOL + blockIdx.x * 256);

    // issue one 8-row group (8KB): 4 x 16B per thread
    auto issue = [&](int g, int buf) {
        const char* src = Wp + (size_t)g * 8 * (NCOL * 4);
#pragma unroll
        for (int i = 0; i < 4; i++) {
            int idx = i * 2048 + tid * 16;           // byte idx within 8KB group
            int r   = idx >> 10;                      // row in group
            int cb  = idx & 1023;                     // col byte
            cp16(wt_sh + buf * 8192 + idx, src + (size_t)r * (NCOL * 4) + cb);
        }
        asm volatile("cp.async.commit_group;");
    };

    // prologue: two groups in flight
    issue(0, 0);
    issue(1, 1);

#pragma unroll
    for (int g = 0; g < 8; g++) {
        if (g + 2 < 8) issue(g + 2, (g + 2) % 3);
        // guarantee group g landed: pending = issued(min(g+2,7)) - g
        if (g < 6)       asm volatile("cp.async.wait_group 2;");
        else if (g == 6) asm volatile("cp.async.wait_group 1;");
        else             asm volatile("cp.async.wait_group 0;");
        __syncthreads();

        const float* wrow = &wt[g % 3][0][0];
#pragma unroll
        for (int r = 0; r < 8; r++) {
            float2 w = *(const float2*)(wrow + r * 256 + tid * 2);
            unsigned long long wx, wy;
            asm("mov.b64 %0, {%1, %1};" : "=l"(wx) : "f"(w.x));
            asm("mov.b64 %0, {%1, %1};" : "=l"(wy) : "f"(w.y));
            const uint32_t ra = xs_sh + (g * 8 + r) * 64;
#pragma unroll
            for (int bh = 0; bh < 4; bh++) {
                unsigned long long xa, xb;   // batches {4bh,4bh+1}, {4bh+2,4bh+3}
                asm("ld.shared.v2.b64 {%0, %1}, [%2];"
                    : "=l"(xa), "=l"(xb) : "r"(ra + bh * 16));
                asm("fma.rn.f32x2 %0, %1, %2, %0;" : "+l"(acc[bh * 4 + 0]) : "l"(xa), "l"(wx));
                asm("fma.rn.f32x2 %0, %1, %2, %0;" : "+l"(acc[bh * 4 + 1]) : "l"(xa), "l"(wy));
                asm("fma.rn.f32x2 %0, %1, %2, %0;" : "+l"(acc[bh * 4 + 2]) : "l"(xb), "l"(wx));
                asm("fma.rn.f32x2 %0, %1, %2, %0;" : "+l"(acc[bh * 4 + 3]) : "l"(xb), "l"(wy));
            }
        }
        __syncthreads();   // all warps done with buffer g%3 before it is re-issued
    }

    float2* P2 = (float2*)part;
#pragma unroll
    for (int bp = 0; bp < 8; bp++) {
        float c0l, c0h, c1l, c1h;
        asm("mov.b64 {%0, %1}, %2;" : "=f"(c0l), "=f"(c0h) : "l"(acc[bp * 2]));
        asm("mov.b64 {%0, %1}, %2;" : "=f"(c1l), "=f"(c1h) : "l"(acc[bp * 2 + 1]));
        P2[(bp * 2 + 0) * (NCOL / 2) + j2] = make_float2(c0l, c1l);
        P2[(bp * 2 + 1) * (NCOL / 2) + j2] = make_float2(c0h, c1h);
    }
}

__global__ __launch_bounds__(128, 8)
void gemm_qkv(const float* __restrict__ x, const float* __restrict__ wq,
              const float* __restrict__ wk, const float* __restrict__ wv)
{
    const float* W = (blockIdx.z == 0) ? wq : (blockIdx.z == 1 ? wk : wv);
    float* part = g_part + ((size_t)blockIdx.z * KS + blockIdx.y) * BN;
    gemm16_body(x, W, part);
}

__global__ __launch_bounds__(128, 8)
void gemm_out(const float* __restrict__ wo)
{
    float* part = g_cpart + (size_t)blockIdx.y * BN;
    gemm16_body(g_ctx, wo, part);
}

__global__ __launch_bounds__(256)
void reduce_qkv()
{
    int i = blockIdx.x * 256 + threadIdx.x;
    if (i < 3 * BN) {
        int mat = i >> 16;
        int r   = i & (BN - 1);
        const float* p = g_part + (size_t)mat * KS * BN + r;
        float s = 0.f;
#pragma unroll 8
        for (int k = 0; k < KS; k++) s += p[(size_t)k * BN];
        g_qkv[i] = s;
    }
}

__global__ __launch_bounds__(256)
void reduce_out(float* __restrict__ out)
{
    int i = blockIdx.x * 256 + threadIdx.x;
    if (i < BN) {
        const float* p = g_cpart + i;
        float s = 0.f;
#pragma unroll 8
        for (int k = 0; k < KS; k++) s += p[(size_t)k * BN];
        __stcs(&out[i], s);
    }
}

// ---------------------------------------------------------------------------
// Fused attention per (b,h), 512 threads — two-pass form (rounds 4/7/9/12/14;
// ~6.8 TB/s effective; single wave of 512 resident blocks). DO NOT SPLIT
// (regressed +30us in rounds 3, 6, 8). K/V streamed with __ldcs; weight
// output written with __stcs (write-once, never re-read).
// ---------------------------------------------------------------------------
__global__ __launch_bounds__(512)
void attn_kernel(const float* __restrict__ ck, const float* __restrict__ cv,
                 const float* __restrict__ mask, float* __restrict__ out)
{
    const int b = blockIdx.x, h = blockIdx.y;
    const int tid = threadIdx.x, lane = tid & 31, wp = tid >> 5;

    __shared__ float sc[SEQ];          // scores -> exp weights
    __shared__ __align__(16) float qs[DH];
    __shared__ float redm[16], reds[16];
    __shared__ __align__(16) float cp[16][DH];

    if (tid < DH) qs[tid] = g_qkv[(size_t)b * NCOL + h * DH + tid];
    __syncthreads();

    const float4 qf = ((const float4*)qs)[lane];
    const float4* kb4 = (const float4*)(ck + ((size_t)b << 24) + (size_t)h * DH);
    const float4* kn4 = (const float4*)(g_qkv + BN + (size_t)b * NCOL + h * DH);
    const float scale = 0.08838834764831845f;                        // 1/sqrt(128)
    float* wout = out + ((size_t)(b * NH + h)) * SEQ;

    // pass 1: scores (16 warps, 256 rows each); streaming K loads
#pragma unroll 4
    for (int k = wp; k < SEQ; k += 16) {
        float4 kf = (k == SEQ - 1) ? kn4[lane]
                                   : __ldcs(&kb4[(size_t)k * (NCOL / 4) + lane]);
        float p = kf.x * qf.x + kf.y * qf.y + kf.z * qf.z + kf.w * qf.w;
        p += __shfl_xor_sync(0xffffffffu, p, 16);
        p += __shfl_xor_sync(0xffffffffu, p, 8);
        p += __shfl_xor_sync(0xffffffffu, p, 4);
        p += __shfl_xor_sync(0xffffffffu, p, 2);
        p += __shfl_xor_sync(0xffffffffu, p, 1);
        if (lane == 0) sc[k] = p * scale + __ldg(&mask[k]);
    }
    __syncthreads();

    // coalesced weight output write (streaming) + max reduce
    float m = -1e30f;
    for (int i = tid; i < SEQ; i += 512) {
        float s = sc[i];
        __stcs(&wout[i], s);
        m = fmaxf(m, s);
    }
#pragma unroll
    for (int o = 16; o; o >>= 1) m = fmaxf(m, __shfl_xor_sync(0xffffffffu, m, o));
    if (lane == 0) redm[wp] = m;
    __syncthreads();
    float M = redm[0];
#pragma unroll
    for (int i = 1; i < 16; i++) M = fmaxf(M, redm[i]);

    float sum = 0.f;
    for (int i = tid; i < SEQ; i += 512) {
        float e = __expf(sc[i] - M);
        sc[i] = e;
        sum += e;
    }
#pragma unroll
    for (int o = 16; o; o >>= 1) sum += __shfl_xor_sync(0xffffffffu, sum, o);
    if (lane == 0) reds[wp] = sum;
    __syncthreads();
    float S = 0.f;
#pragma unroll
    for (int i = 0; i < 16; i++) S += reds[i];
    const float rinv = 1.f / S;

    // pass 2: ctx[d] = sum_k attn[k] * V[b,k,h,d]; 16 k-stripes, streaming
    const float4* vrow4 = (const float4*)(cv + ((size_t)b << 24) + (size_t)h * DH);
    float4 a4 = make_float4(0.f, 0.f, 0.f, 0.f);
    const int k0 = wp * 256;
    const int k1 = k0 + 256 - (wp == 15 ? 1 : 0);   // stripe 15 stops at 4094
#pragma unroll 8
    for (int k = k0; k < k1; k++) {
        float w = sc[k];
        float4 v = __ldcs(&vrow4[(size_t)k * (NCOL / 4) + lane]);
        a4.x += w * v.x; a4.y += w * v.y; a4.z += w * v.z; a4.w += w * v.w;
    }
    if (wp == 15) {
        float w = sc[SEQ - 1];
        float4 v = ((const float4*)(g_qkv + 2 * BN + (size_t)b * NCOL + h * DH))[lane];
        a4.x += w * v.x; a4.y += w * v.y; a4.z += w * v.z; a4.w += w * v.w;
    }
    ((float4*)cp[wp])[lane] = a4;
    __syncthreads();

    if (tid < DH) {
        float s = 0.f;
#pragma unroll
        for (int i = 0; i < 16; i++) s += cp[i][tid];
        g_ctx[(size_t)b * NCOL + h * DH + tid] = s * rinv;
    }
}

// ---------------------------------------------------------------------------
extern "C" void kernel_launch(void* const* d_in, const int* in_sizes, int n_in,
                              void* d_out, int out_size)
{
    const float* x    = (const float*)d_in[0];
    const float* mask = (const float*)d_in[1];
    const float* wq   = (const float*)d_in[2];
    const float* wk   = (const float*)d_in[3];
    const float* wv   = (const float*)d_in[4];
    const float* wo   = (const float*)d_in[5];
    const float* ck   = (const float*)d_in[6];
    const float* cv   = (const float*)d_in[7];
    float* out = (float*)d_out;

    gemm_qkv<<<dim3(16, KS, 3), 128>>>(x, wq, wk, wv);
    reduce_qkv<<<(3 * BN) / 256, 256>>>();
    attn_kernel<<<dim3(BS, NH), 512>>>(ck, cv, mask, out);
    gemm_out<<<dim3(16, KS, 1), 128>>>(wo);
    reduce_out<<<BN / 256, 256>>>(out + WEIGHT_ELEMS);
}